// round 8
// baseline (speedup 1.0000x reference)
#include <cuda_runtime.h>

#define BB 4
#define SS 8192
#define DD 1024
#define ROWS_PB 16   // rows per gather block (1024 thr = 4 row-groups x 256)

// Scratch: selected row index per output slot, per batch.
__device__ int g_sel[BB * SS];
// Per-batch ready flag + completion counter (self-cleaning across replays).
__device__ volatile int g_ready[BB];
__device__ int g_done[BB];

__global__ void __launch_bounds__(1024, 1)
fused_kernel(const float* __restrict__ x,
             const void* __restrict__ boundaries,
             float* __restrict__ out,
             float* __restrict__ out_tail,
             int max_chunks, int rem, int gx) {
    const int bid = blockIdx.x;
    const int t = threadIdx.x;            // 0..1023

    if (bid < BB) {
        // ================= builder for batch b = bid =================
        const int b = bid;

        // ---- dtype fingerprint over first 1024 bytes ----
        // uint8 bool  -> nonzero bytes at positions 1 mod 4
        // int32 (=1)  -> nonzero only at position 0 mod 4
        // float32 1.0 -> bytes 00 00 80 3F: nonzero only at 2,3 mod 4
        __shared__ int s_m1, s_m23;
        if (t == 0) { s_m1 = 0; s_m23 = 0; }
        __syncthreads();
        {
            const unsigned char byte = ((const unsigned char*)boundaries)[t];
            if (byte) {
                const int m = t & 3;
                if (m == 1) atomicAdd(&s_m1, 1);
                else if (m >= 2) atomicAdd(&s_m23, 1);
            }
        }
        __syncthreads();
        const int flag = s_m1 ? 0 : (s_m23 ? 2 : 1);  // 0=bool8 1=i32 2=f32

        // ---- load this thread's 8 flags ----
        unsigned char v[8];
        int local = 0;
        if (flag == 0) {
            const unsigned char* bp =
                (const unsigned char*)boundaries + (size_t)b * SS;
            unsigned long long packed =
                *reinterpret_cast<const unsigned long long*>(bp + (size_t)t * 8);
#pragma unroll
            for (int k = 0; k < 8; k++) {
                v[k] = (unsigned char)(((packed >> (8 * k)) & 0xFFu) != 0);
                local += v[k];
            }
        } else if (flag == 1) {
            const int4* ip = reinterpret_cast<const int4*>(
                (const int*)boundaries + (size_t)b * SS + (size_t)t * 8);
            int4 a = ip[0], c = ip[1];
            v[0] = a.x != 0; v[1] = a.y != 0; v[2] = a.z != 0; v[3] = a.w != 0;
            v[4] = c.x != 0; v[5] = c.y != 0; v[6] = c.z != 0; v[7] = c.w != 0;
#pragma unroll
            for (int k = 0; k < 8; k++) local += v[k];
        } else {
            const float4* fp = reinterpret_cast<const float4*>(
                (const float*)boundaries + (size_t)b * SS + (size_t)t * 8);
            float4 a = fp[0], c = fp[1];
            v[0] = a.x != 0.f; v[1] = a.y != 0.f;
            v[2] = a.z != 0.f; v[3] = a.w != 0.f;
            v[4] = c.x != 0.f; v[5] = c.y != 0.f;
            v[6] = c.z != 0.f; v[7] = c.w != 0.f;
#pragma unroll
            for (int k = 0; k < 8; k++) local += v[k];
        }

        // ---- inclusive warp scan of per-thread counts ----
        const int lane = t & 31, warp = t >> 5;
        int inc = local;
#pragma unroll
        for (int o = 1; o < 32; o <<= 1) {
            int y = __shfl_up_sync(0xFFFFFFFFu, inc, o);
            if (lane >= o) inc += y;
        }

        __shared__ int warp_tot[32];
        __shared__ int warp_off[32];
        __shared__ int s_nt;
        if (lane == 31) warp_tot[warp] = inc;
        __syncthreads();

        if (warp == 0) {
            int w = warp_tot[lane];
            int wi = w;
#pragma unroll
            for (int o = 1; o < 32; o <<= 1) {
                int y = __shfl_up_sync(0xFFFFFFFFu, wi, o);
                if (lane >= o) wi += y;
            }
            warp_off[lane] = wi - w;
            if (lane == 31) s_nt = wi;
        }
        __syncthreads();

        const int nt = s_nt;
        int run = warp_off[warp] + (inc - local);
        const int base_idx = t * 8;
        int* sel = g_sel + b * SS;
#pragma unroll
        for (int k = 0; k < 8; k++) {
            const int idx = base_idx + k;
            if (v[k]) {
                if (run < max_chunks) sel[run] = idx;     // boundary token
                run++;
            } else {
                const int slot = nt + (idx - run);        // non-boundary
                if (slot < max_chunks) sel[slot] = idx;
            }
        }

        if (t == 0 && rem > 0) {
            if (rem == 2 * BB)
                ((long long*)out_tail)[b] = (long long)nt;  // int64 bits
            else
                out_tail[b] = (float)nt;                    // f32 tail
        }

        // publish: all stores globally visible, then raise flag
        __threadfence();
        __syncthreads();
        if (t == 0) g_ready[b] = 1;
        return;
    }

    // ================= gather block =================
    const int gb = bid - BB;
    const int b = gb / gx;
    const int j0 = (gb - b * gx) * ROWS_PB;

    if (t == 0) {
        while (g_ready[b] == 0) { }   // builders are wave-1: always progress
        __threadfence();              // order sel loads after flag
    }
    __syncthreads();

    const int sub = t >> 8;           // 0..3  (row subgroup)
    const int c = t & 255;            // float4 index within row
    const int* __restrict__ sel = g_sel + b * SS;

    int rows[ROWS_PB / 4];
#pragma unroll
    for (int i = 0; i < ROWS_PB / 4; i++) {
        const int j = j0 + sub + 4 * i;
        rows[i] = __ldg(&sel[j < max_chunks ? j : max_chunks - 1]);
    }
    float4 vv[ROWS_PB / 4];
#pragma unroll
    for (int i = 0; i < ROWS_PB / 4; i++)
        vv[i] = __ldcs(reinterpret_cast<const float4*>(
                           x + ((size_t)b * SS + rows[i]) * DD) + c);
#pragma unroll
    for (int i = 0; i < ROWS_PB / 4; i++) {
        const int j = j0 + sub + 4 * i;
        if (j < max_chunks)
            __stcs(reinterpret_cast<float4*>(
                       out + ((size_t)b * max_chunks + j) * DD) + c, vv[i]);
    }

    // ---- self-clean so every graph replay starts from zeroed flags ----
    __syncthreads();
    if (t == 0) {
        const int d = atomicAdd(&g_done[b], 1) + 1;
        if (d == gx) {                 // last gather block of this batch
            g_done[b] = 0;
            __threadfence();
            g_ready[b] = 0;
        }
    }
}

extern "C" void kernel_launch(void* const* d_in, const int* in_sizes, int n_in,
                              void* d_out, int out_size) {
    const float* x = (const float*)d_in[0];
    const void* bnd = d_in[1];
    float* out = (float*)d_out;

    // out layout: [B, max_chunks, D] f32, optionally followed by num_tokens.
    const int max_chunks = out_size / (BB * DD);           // floor
    const int rem = out_size - max_chunks * (BB * DD);     // 0, 4, or 8
    float* tail = out + (size_t)BB * max_chunks * DD;

    const int gx = (max_chunks + ROWS_PB - 1) / ROWS_PB;   // blocks per batch
    fused_kernel<<<BB + BB * gx, 1024>>>(x, bnd, out, tail,
                                         max_chunks, rem, gx);
}

// round 9
// speedup vs baseline: 1.4133x; 1.4133x over previous
#include <cuda_runtime.h>

#define BB 4
#define SS 8192
#define DD 1024
#define RPB 4   // rows per gather block (one float4 per thread per row)

// Scratch: selected row index per output slot, per batch.
__device__ int g_sel[BB * SS];

// One block per batch: (1) fingerprint boundaries dtype from first 1KB,
// (2) block-wide prefix sum over 8192 boundary flags, (3) scatter the
// stable-partition permutation into g_sel. Triggers the dependent gather
// launch as soon as g_sel is published.
__global__ void __launch_bounds__(1024, 1)
build_sel_kernel(const void* __restrict__ boundaries,
                 float* __restrict__ out_tail,   // may be unused (rem==0)
                 int max_chunks, int rem) {
    const int b = blockIdx.x;
    const int t = threadIdx.x;            // 0..1023

    // ---- dtype fingerprint over first 1024 bytes (coalesced, 1B/thread) ----
    // uint8 bool  -> nonzero bytes at positions 1 mod 4
    // int32 (=1)  -> nonzero only at position 0 mod 4
    // float32 1.0 -> bytes 00 00 80 3F: nonzero only at positions 2,3 mod 4
    __shared__ int s_m1, s_m23;
    if (t == 0) { s_m1 = 0; s_m23 = 0; }
    __syncthreads();
    {
        const unsigned char byte = ((const unsigned char*)boundaries)[t];
        if (byte) {
            const int m = t & 3;
            if (m == 1) atomicAdd(&s_m1, 1);
            else if (m >= 2) atomicAdd(&s_m23, 1);
        }
    }
    __syncthreads();
    const int flag = s_m1 ? 0 : (s_m23 ? 2 : 1);   // 0=bool8, 1=i32, 2=f32

    // ---- load this thread's 8 flags ----
    unsigned char v[8];
    int local = 0;
    if (flag == 0) {
        const unsigned char* bp = (const unsigned char*)boundaries + (size_t)b * SS;
        unsigned long long packed =
            *reinterpret_cast<const unsigned long long*>(bp + (size_t)t * 8);
#pragma unroll
        for (int k = 0; k < 8; k++) {
            v[k] = (unsigned char)(((packed >> (8 * k)) & 0xFFu) != 0);
            local += v[k];
        }
    } else if (flag == 1) {
        const int4* ip = reinterpret_cast<const int4*>(
            (const int*)boundaries + (size_t)b * SS + (size_t)t * 8);
        int4 a = ip[0], c = ip[1];
        v[0] = a.x != 0; v[1] = a.y != 0; v[2] = a.z != 0; v[3] = a.w != 0;
        v[4] = c.x != 0; v[5] = c.y != 0; v[6] = c.z != 0; v[7] = c.w != 0;
#pragma unroll
        for (int k = 0; k < 8; k++) local += v[k];
    } else {
        const float4* fp = reinterpret_cast<const float4*>(
            (const float*)boundaries + (size_t)b * SS + (size_t)t * 8);
        float4 a = fp[0], c = fp[1];
        v[0] = a.x != 0.f; v[1] = a.y != 0.f; v[2] = a.z != 0.f; v[3] = a.w != 0.f;
        v[4] = c.x != 0.f; v[5] = c.y != 0.f; v[6] = c.z != 0.f; v[7] = c.w != 0.f;
#pragma unroll
        for (int k = 0; k < 8; k++) local += v[k];
    }

    // ---- inclusive warp scan of per-thread counts ----
    const int lane = t & 31, warp = t >> 5;
    int inc = local;
#pragma unroll
    for (int o = 1; o < 32; o <<= 1) {
        int y = __shfl_up_sync(0xFFFFFFFFu, inc, o);
        if (lane >= o) inc += y;
    }

    __shared__ int warp_tot[32];
    __shared__ int warp_off[32];
    __shared__ int s_nt;
    if (lane == 31) warp_tot[warp] = inc;
    __syncthreads();

    if (warp == 0) {
        int w = warp_tot[lane];
        int wi = w;
#pragma unroll
        for (int o = 1; o < 32; o <<= 1) {
            int y = __shfl_up_sync(0xFFFFFFFFu, wi, o);
            if (lane >= o) wi += y;
        }
        warp_off[lane] = wi - w;          // exclusive warp offset
        if (lane == 31) s_nt = wi;        // total boundary count
    }
    __syncthreads();

    const int nt = s_nt;
    int run = warp_off[warp] + (inc - local);   // exclusive prefix for thread
    const int base_idx = t * 8;
    int* sel = g_sel + b * SS;
#pragma unroll
    for (int k = 0; k < 8; k++) {
        const int idx = base_idx + k;
        if (v[k]) {
            if (run < max_chunks) sel[run] = idx;  // boundary token
            run++;
        } else {
            const int slot = nt + (idx - run);     // non-boundary token
            if (slot < max_chunks) sel[slot] = idx;
        }
    }

    // num_tokens tail, encoding chosen by leftover element count.
    if (t == 0 && rem > 0) {
        if (rem == 2 * BB) {
            ((long long*)out_tail)[b] = (long long)nt;     // int64 bits
        } else {
            out_tail[b] = (float)nt;                       // f32 (rem==BB)
        }
    }

    // Publish g_sel, then allow the dependent gather kernel to proceed.
    __threadfence();
    __syncthreads();
    cudaTriggerProgrammaticLaunchCompletion();
}

// One block per RPB output rows. Each thread: RPB independent 16B
// load/store pairs (MLP=RPB), streaming hints (data touched exactly once).
// Launched with programmatic stream serialization: blocks come up while the
// builder still runs, then gate on cudaGridDependencySynchronize().
__global__ void __launch_bounds__(256)
gather_kernel(const float* __restrict__ x,
              float* __restrict__ out,
              int max_chunks) {
    const int j0 = blockIdx.x * RPB;
    const int b  = blockIdx.y;
    const int t  = threadIdx.x;

    cudaGridDependencySynchronize();   // g_sel published by builder's trigger

    const int* __restrict__ sel = g_sel + b * SS;
    int rows[RPB];
#pragma unroll
    for (int r = 0; r < RPB; r++) {
        const int j = j0 + r;
        rows[r] = __ldg(&sel[j < max_chunks ? j : max_chunks - 1]);
    }

    float4 vv[RPB];
#pragma unroll
    for (int r = 0; r < RPB; r++) {
        vv[r] = __ldcs(reinterpret_cast<const float4*>(
                           x + ((size_t)b * SS + rows[r]) * DD) + t);
    }

#pragma unroll
    for (int r = 0; r < RPB; r++) {
        const int j = j0 + r;
        if (j < max_chunks)
            __stcs(reinterpret_cast<float4*>(
                       out + ((size_t)b * max_chunks + j) * DD) + t, vv[r]);
    }
}

extern "C" void kernel_launch(void* const* d_in, const int* in_sizes, int n_in,
                              void* d_out, int out_size) {
    const float* x = (const float*)d_in[0];
    const void* bnd = d_in[1];
    float* out = (float*)d_out;

    // out layout: [B, max_chunks, D] f32, optionally followed by num_tokens.
    const int max_chunks = out_size / (BB * DD);           // floor
    const int rem = out_size - max_chunks * (BB * DD);     // 0, 4, or 8
    float* tail = out + (size_t)BB * max_chunks * DD;

    build_sel_kernel<<<BB, 1024>>>(bnd, tail, max_chunks, rem);

    // Gather with PDL: launch overlaps the builder; data dependency is
    // enforced in-kernel via cudaGridDependencySynchronize().
    cudaLaunchConfig_t cfg = {};
    cfg.gridDim = dim3((max_chunks + RPB - 1) / RPB, BB);
    cfg.blockDim = dim3(256);
    cudaLaunchAttribute attr[1];
    attr[0].id = cudaLaunchAttributeProgrammaticStreamSerialization;
    attr[0].val.programmaticStreamSerializationAllowed = 1;
    cfg.attrs = attr;
    cfg.numAttrs = 1;
    cudaLaunchKernelEx(&cfg, gather_kernel, x, out, max_chunks);
}